// round 7
// baseline (speedup 1.0000x reference)
#include <cuda_runtime.h>

// PatchesCreate: [64, 384, 384, 3] f32 -> [64, 576, 768] f32
// Direct permutation copy in 256-bit (float8 = 32B) units, persistent
// grid-stride with software pipelining: prefetch next tile's 4 LDG.E.256
// before storing the current tile, so reads stay in flight through the
// store burst. Grid = 148 SMs x 6 CTAs for balanced waves.

static constexpr int TOTAL8 = 64 * 576 * 96;   // 3,538,944 x 32B
static constexpr int TPB    = 256;
static constexpr int UNROLL = 4;
static constexpr int TILE   = TPB * UNROLL;    // 1024 float8 per tile
static constexpr int NTILES = TOTAL8 / TILE;   // 3456 exactly
static constexpr int BLOCKS = 148 * 6;         // 888 persistent CTAs

// i in float8 (32B) units over the output.
__device__ __forceinline__ long long in_off8(int i)
{
    int e     = i % 96;           // float8 within patch
    int t     = i / 96;
    int patch = t % 576;
    int b     = t / 576;

    int gy   = patch / 24;
    int gx   = patch - gy * 24;
    int py   = e / 6;
    int lane = e - py * 6;

    int y = gy * 16 + py;
    return (long long)(b * 384 + y) * 144 + gx * 6 + lane;
}

__device__ __forceinline__ void ldg256(const float* p, float4& a, float4& b)
{
    asm volatile("ld.global.nc.v8.f32 {%0,%1,%2,%3,%4,%5,%6,%7}, [%8];"
                 : "=f"(a.x), "=f"(a.y), "=f"(a.z), "=f"(a.w),
                   "=f"(b.x), "=f"(b.y), "=f"(b.z), "=f"(b.w)
                 : "l"(p));
}

__device__ __forceinline__ void stg256(float* p, const float4& a, const float4& b)
{
    asm volatile("st.global.v8.f32 [%0], {%1,%2,%3,%4,%5,%6,%7,%8};"
                 :: "l"(p),
                    "f"(a.x), "f"(a.y), "f"(a.z), "f"(a.w),
                    "f"(b.x), "f"(b.y), "f"(b.z), "f"(b.w)
                 : "memory");
}

__global__ void __launch_bounds__(TPB)
patches_kernel(const float* __restrict__ in, float* __restrict__ out)
{
    int tile = blockIdx.x;

    // Prologue: issue loads for first tile.
    float4 a[UNROLL], b[UNROLL];
    int base = tile * TILE + threadIdx.x;
#pragma unroll
    for (int u = 0; u < UNROLL; ++u)
        ldg256(in + in_off8(base + u * TPB) * 8, a[u], b[u]);

    while (true) {
        int next = tile + BLOCKS;

        if (next < NTILES) {
            // Prefetch next tile (front-batched, independent of a/b use).
            float4 na[UNROLL], nb[UNROLL];
            int nbase = next * TILE + threadIdx.x;
#pragma unroll
            for (int u = 0; u < UNROLL; ++u)
                ldg256(in + in_off8(nbase + u * TPB) * 8, na[u], nb[u]);

            // Store current tile.
#pragma unroll
            for (int u = 0; u < UNROLL; ++u)
                stg256(out + (long long)(base + u * TPB) * 8, a[u], b[u]);

#pragma unroll
            for (int u = 0; u < UNROLL; ++u) { a[u] = na[u]; b[u] = nb[u]; }
            tile = next;
            base = nbase;
        } else {
            // Epilogue: store last tile and exit.
#pragma unroll
            for (int u = 0; u < UNROLL; ++u)
                stg256(out + (long long)(base + u * TPB) * 8, a[u], b[u]);
            break;
        }
    }
}

extern "C" void kernel_launch(void* const* d_in, const int* in_sizes, int n_in,
                              void* d_out, int out_size)
{
    (void)in_sizes; (void)n_in; (void)out_size;
    const float* in  = (const float*)d_in[0];
    float*       out = (float*)d_out;

    patches_kernel<<<BLOCKS, TPB>>>(in, out);
}

// round 8
// speedup vs baseline: 1.0508x; 1.0508x over previous
#include <cuda_runtime.h>

// PatchesCreate: [64, 384, 384, 3] f32 -> [64, 576, 768] f32
// Converged design (R5): direct permutation copy in 256-bit (float8 = 32B)
// units. Patch row = 192B = 6 x 32B chunks, all 32B-aligned.
// Per-thread: 4 independent LDG.E.256 front-batched (MLP), then 4
// STG.E.256 with streaming hint. Flat grid, no tail.
// Measured: 29.5us kernel = 7.67 TB/s actual DRAM = 96% of 8TB/s spec.

static constexpr int TOTAL8 = 64 * 576 * 96;   // 3,538,944 x 32B
static constexpr int TPB    = 256;
static constexpr int UNROLL = 4;
static constexpr int TILE   = TPB * UNROLL;    // 1024
static constexpr int BLOCKS = TOTAL8 / TILE;   // 3456 exactly, no tail

// i in float8 (32B) units over the output.
__device__ __forceinline__ long long in_off8(int i)
{
    int e     = i % 96;           // float8 within patch (96 per patch)
    int t     = i / 96;
    int patch = t % 576;
    int b     = t / 576;

    int gy   = patch / 24;
    int gx   = patch - gy * 24;
    int py   = e / 6;
    int lane = e - py * 6;

    int y = gy * 16 + py;
    return (long long)(b * 384 + y) * 144 + gx * 6 + lane;  // float8 units
}

__device__ __forceinline__ void ldg256(const float* p, float4& a, float4& b)
{
    asm volatile("ld.global.nc.v8.f32 {%0,%1,%2,%3,%4,%5,%6,%7}, [%8];"
                 : "=f"(a.x), "=f"(a.y), "=f"(a.z), "=f"(a.w),
                   "=f"(b.x), "=f"(b.y), "=f"(b.z), "=f"(b.w)
                 : "l"(p));
}

__device__ __forceinline__ void stg256(float* p, const float4& a, const float4& b)
{
    asm volatile("st.global.cs.v8.f32 [%0], {%1,%2,%3,%4,%5,%6,%7,%8};"
                 :: "l"(p),
                    "f"(a.x), "f"(a.y), "f"(a.z), "f"(a.w),
                    "f"(b.x), "f"(b.y), "f"(b.z), "f"(b.w)
                 : "memory");
}

__global__ void __launch_bounds__(TPB)
patches_kernel(const float* __restrict__ in, float* __restrict__ out)
{
    int base = blockIdx.x * TILE + threadIdx.x;

    const float* src[UNROLL];
#pragma unroll
    for (int u = 0; u < UNROLL; ++u)
        src[u] = in + in_off8(base + u * TPB) * 8;

    float4 a[UNROLL], b[UNROLL];
#pragma unroll
    for (int u = 0; u < UNROLL; ++u)
        ldg256(src[u], a[u], b[u]);

#pragma unroll
    for (int u = 0; u < UNROLL; ++u)
        stg256(out + (long long)(base + u * TPB) * 8, a[u], b[u]);
}

extern "C" void kernel_launch(void* const* d_in, const int* in_sizes, int n_in,
                              void* d_out, int out_size)
{
    (void)in_sizes; (void)n_in; (void)out_size;
    const float* in  = (const float*)d_in[0];
    float*       out = (float*)d_out;

    patches_kernel<<<BLOCKS, TPB>>>(in, out);
}